// round 12
// baseline (speedup 1.0000x reference)
#include <cuda_runtime.h>

// Problem constants (from reference: B=16, L=192, E=128, T=25)
#define BB     16
#define LL     192
#define EE     128
#define TT     25
#define NI     (LL - TT - 1)         // 166 block rows per batch (even)
#define LOUT   (TT + 1 + NI * LL)    // 31898 output rows per batch
#define E2     (EE / 2)              // 64 float2 per row
#define NZ     24                    // l-slices per batch
#define LCH    (LL / NZ)             // 8 l-rows per slice
#define NCHUNK 2                     // i-chunks
#define IC     (NI / NCHUNK)         // 83 i-values per chunk

__device__ __forceinline__ float sigmoidf_fast(float z) {
    return __frcp_rn(1.0f + __expf(-z));
}

// Single kernel. Grid (2, 16, 24) = 768 CTAs (one wave), 256 threads.
// CTA = (i-chunk, batch b, l-slice of 8 rows). Each thread owns lane
// e2 = tid%64 and two l-rows (lsub, lsub+4); it computes its 2 float2 of
// s0 = sigmoid(x*(W0-W1)+(b0-b1)) ONCE into registers, then loops over the
// 83 i-values of its chunk: reload xi/xp (L1/L2-hit, x is 1.5 MB) and emit
// 2 streaming STG.64 per i. No scratch table, no second kernel, no sync.
__global__ void __launch_bounds__(256, 6)
fused_kernel(const float* __restrict__ x,
             const float* __restrict__ W,
             const float* __restrict__ bvec,
             float* __restrict__ out) {
    const int chunk = blockIdx.x;    // 0..1
    const int b     = blockIdx.y;    // 0..15
    const int zl    = blockIdx.z;    // 0..23
    const int tid   = threadIdx.x;
    const int lsub  = tid >> 6;      // 0..3
    const int e2    = tid & 63;      // 0..63

    const float2* __restrict__ x2 = reinterpret_cast<const float2*>(x);
    float2* __restrict__ o2       = reinterpret_cast<float2*>(out);

    const float dw = W[0] - W[1];
    const float db = bvec[0] - bvec[1];

    const int lbeg = zl * LCH;
    const int la = lbeg + lsub;       // first owned l-row
    const int lb = la + 4;            // second owned l-row

    // s0 for the two owned (l, e2) positions — registers only.
    float2 va = __ldg(&x2[((size_t)b * LL + la) * E2 + e2]);
    float2 vb = __ldg(&x2[((size_t)b * LL + lb) * E2 + e2]);
    float2 sa, sb;
    sa.x = sigmoidf_fast(fmaf(va.x, dw, db));
    sa.y = sigmoidf_fast(fmaf(va.y, dw, db));
    sb.x = sigmoidf_fast(fmaf(vb.x, dw, db));
    sb.y = sigmoidf_fast(fmaf(vb.y, dw, db));

    // Head copy (out[:, :26, :] = x[:, :26, :]), spread over chunk-0 CTAs:
    // slice zl copies row t=zl (threads 0..127 as 2 l-subgroups x 64 lanes),
    // and rows t=zl+24 handled by zl<2 via the second half of the block.
    if (chunk == 0) {
        int t = (tid < 128) ? zl : (zl + NZ);
        if (t <= TT) {
            int lane = tid & 63;
            int half = (tid >> 6) & 1;          // two 64-lane groups per t... 
            // each row has 64 float2; use lane for the float2 index, and the
            // spare 'half' bit is folded by having groups 0/1 and 2/3 write
            // the same row (benign duplicate) — keep it simple and exact:
            if (((tid >> 6) & 1) == 0) {
                float2 h = __ldg(&x2[((size_t)b * LL + t) * E2 + lane]);
                o2[((size_t)b * LOUT + t) * E2 + lane] = h;
            }
            (void)half;
        }
    }

    // Main stream over this chunk's i-values.
    const int ibeg = chunk * IC;
    const size_t outrow0 = (size_t)b * LOUT + (TT + 1);

    // Hoisted pointers, advanced per i.
    const float2* __restrict__ xi = x2 + ((size_t)b * LL + (TT + 1 + ibeg)) * E2 + e2;
    const float2* __restrict__ xp = x2 + ((size_t)b * LL + (ibeg + 1)) * E2 + e2;
    float2* __restrict__ qa = o2 + (outrow0 + (size_t)ibeg * LL + la) * E2 + e2;
    // qb = qa + 4 rows (lb = la + 4)

#pragma unroll 4
    for (int i = 0; i < IC; i++) {
        float2 a = __ldg(xi);
        float2 p = __ldg(xp);
        float2 d = make_float2(a.x - p.x, a.y - p.y);
        float2 oa, ob;
        oa.x = fmaf(d.x, sa.x, p.x);
        oa.y = fmaf(d.y, sa.y, p.y);
        ob.x = fmaf(d.x, sb.x, p.x);
        ob.y = fmaf(d.y, sb.y, p.y);
        __stcs(qa, oa);
        __stcs(qa + 4 * E2, ob);
        xi += E2;                 // next xi row
        xp += E2;                 // next xp row
        qa += (size_t)LL * E2;    // next i output block
    }
}

extern "C" void kernel_launch(void* const* d_in, const int* in_sizes, int n_in,
                              void* d_out, int out_size) {
    const float* x  = (const float*)d_in[0];
    const float* W  = (const float*)d_in[1];
    const float* bv = (const float*)d_in[2];
    float* out = (float*)d_out;

    dim3 grid(NCHUNK, BB, NZ);   // (2, 16, 24) = 768 CTAs, single wave
    fused_kernel<<<grid, 256>>>(x, W, bv, out);
}

// round 13
// speedup vs baseline: 1.1788x; 1.1788x over previous
#include <cuda_runtime.h>

// Problem constants (from reference: B=16, L=192, E=128, T=25)
#define BB   16
#define LL   192
#define EE   128
#define TT   25
#define NI   (LL - TT - 1)          // 166 block rows per batch (even)
#define LOUT (TT + 1 + NI * LL)     // 31898 output rows per batch
#define E2   (EE / 2)               // 64 float2 per row
#define E4   (EE / 4)               // 32 float4 per row
#define G    2                      // i-values per CTA (166 % 2 == 0, no tail)
#define NZ   16                     // l-slices per (tile,b)
#define LCH  (LL / NZ)              // 12 l-values per slice

// s0 table: sigmoid(x*(W0-W1)+(b0-b1)). 1.5 MB, L2-resident.
__device__ __align__(16) float g_S[BB * LL * EE];

__device__ __forceinline__ float sigmoidf_fast(float z) {
    return __frcp_rn(1.0f + __expf(-z));
}

// Kernel 1 (producer): S table (float4-vectorized, 384 CTAs) + head copy.
// Triggers the dependent launch as soon as S writes are fenced; head-copy
// tail overlaps with the consumer's prologue.
__global__ void __launch_bounds__(256)
prep_kernel(const float* __restrict__ x,
            const float* __restrict__ W,
            const float* __restrict__ bvec,
            float* __restrict__ out) {
    const int idx = blockIdx.x * blockDim.x + threadIdx.x;   // 0..98303
    const float dw = W[0] - W[1];
    const float db = bvec[0] - bvec[1];

    const float4* __restrict__ x4 = reinterpret_cast<const float4*>(x);
    float4* __restrict__ S4 = reinterpret_cast<float4*>(g_S);

    float4 v = __ldg(&x4[idx]);
    float4 s;
    s.x = sigmoidf_fast(fmaf(v.x, dw, db));
    s.y = sigmoidf_fast(fmaf(v.y, dw, db));
    s.z = sigmoidf_fast(fmaf(v.z, dw, db));
    s.w = sigmoidf_fast(fmaf(v.w, dw, db));
    S4[idx] = s;

    __threadfence();
    cudaTriggerProgrammaticLaunchCompletion();

    // Head copy: out[:, :26, :] = x[:, :26, :]  (13312 float4s)
    if (idx < BB * (TT + 1) * E4) {
        int e = idx % E4;
        int t = (idx / E4) % (TT + 1);
        int b = idx / (E4 * (TT + 1));
        float4 h = __ldg(&x4[((size_t)b * LL + t) * E4 + e]);
        reinterpret_cast<float4*>(out)[((size_t)b * LOUT + t) * E4 + e] = h;
    }
}

// Kernel 2 (consumer): blocks[b,i,l,:] = fma(xi - xp, s0[b,l,:], xp)
// Grid (83,16,16) = 21248 CTAs, 256 threads (fine granularity for even
// store-stream spread). e2 = tid%64 is the float2 lane, lsub = tid/64 covers
// 4 l's per step (3 steps). Entire prologue + pointer setup hoisted above the
// PDL grid-dependency sync; inner body 1 LDG.64 + 4 FMA + 2 STG.64 streaming.
__global__ void __launch_bounds__(256, 8)
blocks_kernel(const float* __restrict__ x, float* __restrict__ out) {
    const int b    = blockIdx.y;
    const int tile = blockIdx.x;
    const int zl   = blockIdx.z;
    const int tid  = threadIdx.x;
    const int lsub = tid >> 6;       // 0..3
    const int e2   = tid & 63;       // 0..63

    const float2* __restrict__ x2 = reinterpret_cast<const float2*>(x);

    const int i0 = tile * G;
    const int i1 = i0 + 1;

    // Prologue (independent of g_S) — overlaps with prep via PDL.
    float2 a0 = __ldg(&x2[((size_t)b * LL + (TT + 1 + i0)) * E2 + e2]);
    float2 p0 = __ldg(&x2[((size_t)b * LL + (i0 + 1)) * E2 + e2]);
    float2 a1 = __ldg(&x2[((size_t)b * LL + (TT + 1 + i1)) * E2 + e2]);
    float2 p1 = __ldg(&x2[((size_t)b * LL + (i1 + 1)) * E2 + e2]);
    float2 d0 = make_float2(a0.x - p0.x, a0.y - p0.y);
    float2 d1 = make_float2(a1.x - p1.x, a1.y - p1.y);

    const int lbeg = zl * LCH;
    const size_t outrow0 = (size_t)b * LOUT + (TT + 1);

    // Pointer setup also hoisted above the sync.
    const float2* __restrict__ sp =
        reinterpret_cast<const float2*>(g_S) +
        ((size_t)b * LL + lbeg + lsub) * E2 + e2;
    float2* __restrict__ q0 =
        reinterpret_cast<float2*>(out) +
        (outrow0 + (size_t)i0 * LL + lbeg + lsub) * E2 + e2;
    float2* __restrict__ q1 =
        reinterpret_cast<float2*>(out) +
        (outrow0 + (size_t)i1 * LL + lbeg + lsub) * E2 + e2;

    // Wait for prep's triggered completion (S table visible after this).
    cudaGridDependencySynchronize();

#pragma unroll
    for (int it = 0; it < LCH / 4; it++) {
        float2 s = __ldg(sp);
        float2 o0, o1;
        o0.x = fmaf(d0.x, s.x, p0.x);
        o0.y = fmaf(d0.y, s.y, p0.y);
        o1.x = fmaf(d1.x, s.x, p1.x);
        o1.y = fmaf(d1.y, s.y, p1.y);
        __stcs(q0, o0);
        __stcs(q1, o1);
        sp += 4 * E2;
        q0 += 4 * E2;
        q1 += 4 * E2;
    }
}

extern "C" void kernel_launch(void* const* d_in, const int* in_sizes, int n_in,
                              void* d_out, int out_size) {
    const float* x  = (const float*)d_in[0];
    const float* W  = (const float*)d_in[1];
    const float* bv = (const float*)d_in[2];
    float* out = (float*)d_out;

    // Producer: 98304 float4s -> 384 blocks of 256.
    prep_kernel<<<(BB * LL * E4 + 255) / 256, 256>>>(x, W, bv, out);

    // Consumer with programmatic dependent launch.
    cudaLaunchAttribute attr[1];
    attr[0].id = cudaLaunchAttributeProgrammaticStreamSerialization;
    attr[0].val.programmaticStreamSerializationAllowed = 1;

    cudaLaunchConfig_t cfg = {};
    cfg.gridDim  = dim3(NI / G, BB, NZ);   // (83, 16, 16) = 21248 CTAs
    cfg.blockDim = dim3(256, 1, 1);
    cfg.dynamicSmemBytes = 0;
    cfg.stream = 0;
    cfg.attrs = attr;
    cfg.numAttrs = 1;

    cudaLaunchKernelEx(&cfg, blocks_kernel, x, out);
}

// round 14
// speedup vs baseline: 1.1893x; 1.0089x over previous
#include <cuda_runtime.h>

// Problem constants (from reference: B=16, L=192, E=128, T=25)
#define BB   16
#define LL   192
#define EE   128
#define TT   25
#define NI   (LL - TT - 1)          // 166 block rows per batch (even)
#define LOUT (TT + 1 + NI * LL)     // 31898 output rows per batch
#define E2   (EE / 2)               // 64 float2 per row
#define E4   (EE / 4)               // 32 float4 per row
#define G    2                      // i-values per CTA (166 % 2 == 0, no tail)
#define NZ   8                      // l-slices per (tile,b)
#define LCH  (LL / NZ)              // 24 l-values per slice

// s0 table: sigmoid(x*(W0-W1)+(b0-b1)). 1.5 MB, L2-resident.
__device__ __align__(16) float g_S[BB * LL * EE];

__device__ __forceinline__ float sigmoidf_fast(float z) {
    return __frcp_rn(1.0f + __expf(-z));
}

// Kernel 1 (producer): S table ONLY — minimal critical path before the
// PDL trigger. 384 CTAs, one float4 per thread, no conditionals.
__global__ void __launch_bounds__(256)
prep_kernel(const float* __restrict__ x,
            const float* __restrict__ W,
            const float* __restrict__ bvec) {
    const int idx = blockIdx.x * blockDim.x + threadIdx.x;   // 0..98303
    const float dw = W[0] - W[1];
    const float db = bvec[0] - bvec[1];

    const float4* __restrict__ x4 = reinterpret_cast<const float4*>(x);
    float4* __restrict__ S4 = reinterpret_cast<float4*>(g_S);

    float4 v = __ldg(&x4[idx]);
    float4 s;
    s.x = sigmoidf_fast(fmaf(v.x, dw, db));
    s.y = sigmoidf_fast(fmaf(v.y, dw, db));
    s.z = sigmoidf_fast(fmaf(v.z, dw, db));
    s.w = sigmoidf_fast(fmaf(v.w, dw, db));
    S4[idx] = s;

    __threadfence();
    cudaTriggerProgrammaticLaunchCompletion();
}

// Kernel 2 (consumer): blocks[b,i,l,:] = fma(xi - xp, s0[b,l,:], xp)
// Grid (83,16,8) = 10624 CTAs, 256 threads. Everything that does not depend
// on g_S — xi/xp prologue, pointer setup, AND the head copy (done by the 128
// tile==0 CTAs) — runs before cudaGridDependencySynchronize(), fully
// overlapped with the producer via PDL. Inner body: 1 LDG.64 + 4 FMA +
// 2 STG.64 streaming (__stcs keeps L2 clean for hot reads on warm replays).
__global__ void __launch_bounds__(256, 8)
blocks_kernel(const float* __restrict__ x, float* __restrict__ out) {
    const int b    = blockIdx.y;
    const int tile = blockIdx.x;
    const int zl   = blockIdx.z;
    const int tid  = threadIdx.x;
    const int lsub = tid >> 6;       // 0..3
    const int e2   = tid & 63;       // 0..63

    const float2* __restrict__ x2 = reinterpret_cast<const float2*>(x);
    float2* __restrict__ o2       = reinterpret_cast<float2*>(out);

    const int i0 = tile * G;
    const int i1 = i0 + 1;

    // --- Overlap window (independent of g_S) ---

    // Head copy: out[:, :26, :] = x[:, :26, :], done by tile==0 CTAs.
    // Row t = zl + 8*lsub covers 0..25 exactly once across (zl, lsub).
    if (tile == 0) {
        int t = zl + 8 * lsub;
        if (t <= TT) {
            float2 h = __ldg(&x2[((size_t)b * LL + t) * E2 + e2]);
            __stcs(&o2[((size_t)b * LOUT + t) * E2 + e2], h);
        }
    }

    // xi/xp prologue.
    float2 a0 = __ldg(&x2[((size_t)b * LL + (TT + 1 + i0)) * E2 + e2]);
    float2 p0 = __ldg(&x2[((size_t)b * LL + (i0 + 1)) * E2 + e2]);
    float2 a1 = __ldg(&x2[((size_t)b * LL + (TT + 1 + i1)) * E2 + e2]);
    float2 p1 = __ldg(&x2[((size_t)b * LL + (i1 + 1)) * E2 + e2]);
    float2 d0 = make_float2(a0.x - p0.x, a0.y - p0.y);
    float2 d1 = make_float2(a1.x - p1.x, a1.y - p1.y);

    const int lbeg = zl * LCH;
    const size_t outrow0 = (size_t)b * LOUT + (TT + 1);

    const float2* __restrict__ sp =
        reinterpret_cast<const float2*>(g_S) +
        ((size_t)b * LL + lbeg + lsub) * E2 + e2;
    float2* __restrict__ q0 = o2 + (outrow0 + (size_t)i0 * LL + lbeg + lsub) * E2 + e2;
    float2* __restrict__ q1 = o2 + (outrow0 + (size_t)i1 * LL + lbeg + lsub) * E2 + e2;

    // --- Wait for producer, then stream ---
    cudaGridDependencySynchronize();

#pragma unroll
    for (int it = 0; it < LCH / 4; it++) {
        float2 s = __ldg(sp);
        float2 o0, o1;
        o0.x = fmaf(d0.x, s.x, p0.x);
        o0.y = fmaf(d0.y, s.y, p0.y);
        o1.x = fmaf(d1.x, s.x, p1.x);
        o1.y = fmaf(d1.y, s.y, p1.y);
        __stcs(q0, o0);
        __stcs(q1, o1);
        sp += 4 * E2;
        q0 += 4 * E2;
        q1 += 4 * E2;
    }
}

extern "C" void kernel_launch(void* const* d_in, const int* in_sizes, int n_in,
                              void* d_out, int out_size) {
    const float* x  = (const float*)d_in[0];
    const float* W  = (const float*)d_in[1];
    const float* bv = (const float*)d_in[2];
    float* out = (float*)d_out;

    // Producer: 98304 float4s -> 384 blocks of 256. S-table only.
    prep_kernel<<<(BB * LL * E4 + 255) / 256, 256>>>(x, W, bv);

    // Consumer with programmatic dependent launch.
    cudaLaunchAttribute attr[1];
    attr[0].id = cudaLaunchAttributeProgrammaticStreamSerialization;
    attr[0].val.programmaticStreamSerializationAllowed = 1;

    cudaLaunchConfig_t cfg = {};
    cfg.gridDim  = dim3(NI / G, BB, NZ);   // (83, 16, 8) = 10624 CTAs
    cfg.blockDim = dim3(256, 1, 1);
    cfg.dynamicSmemBytes = 0;
    cfg.stream = 0;
    cfg.attrs = attr;
    cfg.numAttrs = 1;

    cudaLaunchKernelEx(&cfg, blocks_kernel, x, out);
}

// round 15
// speedup vs baseline: 1.1911x; 1.0015x over previous
#include <cuda_runtime.h>

// Problem constants (from reference: B=16, L=192, E=128, T=25)
#define BB   16
#define LL   192
#define EE   128
#define TT   25
#define NI   (LL - TT - 1)          // 166 block rows per batch (even)
#define LOUT (TT + 1 + NI * LL)     // 31898 output rows per batch
#define E2   (EE / 2)               // 64 float2 per row
#define E4   (EE / 4)               // 32 float4 per row
#define G    2                      // i-values per CTA (166 % 2 == 0, no tail)
#define NZ   16                     // l-slices per (tile,b)
#define LCH  (LL / NZ)              // 12 l-values per slice

// s0 table: sigmoid(x*(W0-W1)+(b0-b1)). 1.5 MB, L2-resident.
__device__ __align__(16) float g_S[BB * LL * EE];

__device__ __forceinline__ float sigmoidf_fast(float z) {
    return __frcp_rn(1.0f + __expf(-z));
}

// Kernel 1 (producer): S table ONLY — minimal critical path before the
// PDL trigger. 384 CTAs, one float4 per thread, no conditionals.
__global__ void __launch_bounds__(256)
prep_kernel(const float* __restrict__ x,
            const float* __restrict__ W,
            const float* __restrict__ bvec) {
    const int idx = blockIdx.x * blockDim.x + threadIdx.x;   // 0..98303
    const float dw = W[0] - W[1];
    const float db = bvec[0] - bvec[1];

    const float4* __restrict__ x4 = reinterpret_cast<const float4*>(x);
    float4* __restrict__ S4 = reinterpret_cast<float4*>(g_S);

    float4 v = __ldg(&x4[idx]);
    float4 s;
    s.x = sigmoidf_fast(fmaf(v.x, dw, db));
    s.y = sigmoidf_fast(fmaf(v.y, dw, db));
    s.z = sigmoidf_fast(fmaf(v.z, dw, db));
    s.w = sigmoidf_fast(fmaf(v.w, dw, db));
    S4[idx] = s;

    __threadfence();
    cudaTriggerProgrammaticLaunchCompletion();
}

// Kernel 2 (consumer): blocks[b,i,l,:] = fma(xi - xp, s0[b,l,:], xp)
// Grid (83,16,16) = 21248 CTAs, 256 threads (fastest raw config, R13).
// Everything independent of g_S — head copy (tile==0 CTAs), xi/xp prologue,
// pointer setup — runs before cudaGridDependencySynchronize(), overlapped
// with the producer via PDL. Inner body: 1 LDG.64 + 4 FMA + 2 STG.64
// streaming (__stcs keeps L2 clean for hot reads on warm replays).
__global__ void __launch_bounds__(256, 8)
blocks_kernel(const float* __restrict__ x, float* __restrict__ out) {
    const int b    = blockIdx.y;
    const int tile = blockIdx.x;
    const int zl   = blockIdx.z;     // 0..15
    const int tid  = threadIdx.x;
    const int lsub = tid >> 6;       // 0..3
    const int e2   = tid & 63;       // 0..63

    const float2* __restrict__ x2 = reinterpret_cast<const float2*>(x);
    float2* __restrict__ o2       = reinterpret_cast<float2*>(out);

    const int i0 = tile * G;
    const int i1 = i0 + 1;

    // --- Overlap window (independent of g_S) ---

    // Head copy: out[:, :26, :] = x[:, :26, :], tile==0 CTAs only.
    // Row t = zl + 16*lsub covers 0..25 exactly once over (zl in [0,16), lsub in {0,1}).
    if (tile == 0) {
        int t = zl + 16 * lsub;
        if (t <= TT) {
            float2 h = __ldg(&x2[((size_t)b * LL + t) * E2 + e2]);
            __stcs(&o2[((size_t)b * LOUT + t) * E2 + e2], h);
        }
    }

    // xi/xp prologue.
    float2 a0 = __ldg(&x2[((size_t)b * LL + (TT + 1 + i0)) * E2 + e2]);
    float2 p0 = __ldg(&x2[((size_t)b * LL + (i0 + 1)) * E2 + e2]);
    float2 a1 = __ldg(&x2[((size_t)b * LL + (TT + 1 + i1)) * E2 + e2]);
    float2 p1 = __ldg(&x2[((size_t)b * LL + (i1 + 1)) * E2 + e2]);
    float2 d0 = make_float2(a0.x - p0.x, a0.y - p0.y);
    float2 d1 = make_float2(a1.x - p1.x, a1.y - p1.y);

    const int lbeg = zl * LCH;
    const size_t outrow0 = (size_t)b * LOUT + (TT + 1);

    const float2* __restrict__ sp =
        reinterpret_cast<const float2*>(g_S) +
        ((size_t)b * LL + lbeg + lsub) * E2 + e2;
    float2* __restrict__ q0 = o2 + (outrow0 + (size_t)i0 * LL + lbeg + lsub) * E2 + e2;
    float2* __restrict__ q1 = o2 + (outrow0 + (size_t)i1 * LL + lbeg + lsub) * E2 + e2;

    // --- Wait for producer, then stream ---
    cudaGridDependencySynchronize();

#pragma unroll
    for (int it = 0; it < LCH / 4; it++) {   // 3 iterations
        float2 s = __ldg(sp);
        float2 o0, o1;
        o0.x = fmaf(d0.x, s.x, p0.x);
        o0.y = fmaf(d0.y, s.y, p0.y);
        o1.x = fmaf(d1.x, s.x, p1.x);
        o1.y = fmaf(d1.y, s.y, p1.y);
        __stcs(q0, o0);
        __stcs(q1, o1);
        sp += 4 * E2;
        q0 += 4 * E2;
        q1 += 4 * E2;
    }
}

extern "C" void kernel_launch(void* const* d_in, const int* in_sizes, int n_in,
                              void* d_out, int out_size) {
    const float* x  = (const float*)d_in[0];
    const float* W  = (const float*)d_in[1];
    const float* bv = (const float*)d_in[2];
    float* out = (float*)d_out;

    // Producer: 98304 float4s -> 384 blocks of 256. S-table only.
    prep_kernel<<<(BB * LL * E4 + 255) / 256, 256>>>(x, W, bv);

    // Consumer with programmatic dependent launch.
    cudaLaunchAttribute attr[1];
    attr[0].id = cudaLaunchAttributeProgrammaticStreamSerialization;
    attr[0].val.programmaticStreamSerializationAllowed = 1;

    cudaLaunchConfig_t cfg = {};
    cfg.gridDim  = dim3(NI / G, BB, NZ);   // (83, 16, 16) = 21248 CTAs
    cfg.blockDim = dim3(256, 1, 1);
    cfg.dynamicSmemBytes = 0;
    cfg.stream = 0;
    cfg.attrs = attr;
    cfg.numAttrs = 1;

    cudaLaunchKernelEx(&cfg, blocks_kernel, x, out);
}

// round 16
// speedup vs baseline: 1.2136x; 1.0189x over previous
#include <cuda_runtime.h>

// Problem constants (from reference: B=16, L=192, E=128, T=25)
#define BB   16
#define LL   192
#define EE   128
#define TT   25
#define NI   (LL - TT - 1)          // 166 block rows per batch (even)
#define LOUT (TT + 1 + NI * LL)     // 31898 output rows per batch
#define E2   (EE / 2)               // 64 float2 per row
#define E4   (EE / 4)               // 32 float4 per row
#define G    2                      // i-values per CTA (166 % 2 == 0, no tail)
#define NZ   16                     // l-slices per (tile,b)
#define LCH  (LL / NZ)              // 12 l-values per slice

// s0 table: sigmoid(x*(W0-W1)+(b0-b1)). 1.5 MB, L2-resident.
__device__ __align__(16) float g_S[BB * LL * EE];

// sigmoid(z) = 0.5*tanh(z/2) + 0.5 using the single-MUFU tanh.approx.f32
// (halves producer MUFU ops vs EX2+RCP; |err| ~ 2^-11, fine vs 1e-3 gate).
__device__ __forceinline__ float sigmoid_tanh(float z) {
    float t;
    asm("tanh.approx.f32 %0, %1;" : "=f"(t) : "f"(z * 0.5f));
    return fmaf(0.5f, t, 0.5f);
}

// Kernel 1 (producer): S table ONLY — minimal critical path before the
// PDL trigger. 384 CTAs, one float4 per thread, no conditionals.
__global__ void __launch_bounds__(256)
prep_kernel(const float* __restrict__ x,
            const float* __restrict__ W,
            const float* __restrict__ bvec) {
    const int idx = blockIdx.x * blockDim.x + threadIdx.x;   // 0..98303
    const float dw = W[0] - W[1];
    const float db = bvec[0] - bvec[1];

    const float4* __restrict__ x4 = reinterpret_cast<const float4*>(x);
    float4* __restrict__ S4 = reinterpret_cast<float4*>(g_S);

    float4 v = __ldg(&x4[idx]);
    float4 s;
    s.x = sigmoid_tanh(fmaf(v.x, dw, db));
    s.y = sigmoid_tanh(fmaf(v.y, dw, db));
    s.z = sigmoid_tanh(fmaf(v.z, dw, db));
    s.w = sigmoid_tanh(fmaf(v.w, dw, db));
    S4[idx] = s;

    __threadfence();
    cudaTriggerProgrammaticLaunchCompletion();
}

// Kernel 2 (consumer): blocks[b,i,l,:] = fma(xi - xp, s0[b,l,:], xp)
// Grid (83,16,16) = 21248 CTAs, 256 threads (fastest raw config).
// Everything independent of g_S — head copy (tile==0 CTAs), xi/xp prologue,
// pointer setup — runs before cudaGridDependencySynchronize(), overlapped
// with the producer via PDL. Inner body: 1 LDG.64 + 4 FMA + 2 STG.64
// streaming (__stcs keeps L2 clean for hot reads on warm replays).
__global__ void __launch_bounds__(256, 8)
blocks_kernel(const float* __restrict__ x, float* __restrict__ out) {
    const int b    = blockIdx.y;
    const int tile = blockIdx.x;
    const int zl   = blockIdx.z;     // 0..15
    const int tid  = threadIdx.x;
    const int lsub = tid >> 6;       // 0..3
    const int e2   = tid & 63;       // 0..63

    const float2* __restrict__ x2 = reinterpret_cast<const float2*>(x);
    float2* __restrict__ o2       = reinterpret_cast<float2*>(out);

    const int i0 = tile * G;
    const int i1 = i0 + 1;

    // --- Overlap window (independent of g_S) ---

    // Head copy: out[:, :26, :] = x[:, :26, :], tile==0 CTAs only.
    // Row t = zl + 16*lsub covers 0..25 exactly once over (zl, lsub in {0,1}).
    if (tile == 0) {
        int t = zl + 16 * lsub;
        if (t <= TT) {
            float2 h = __ldg(&x2[((size_t)b * LL + t) * E2 + e2]);
            __stcs(&o2[((size_t)b * LOUT + t) * E2 + e2], h);
        }
    }

    // xi/xp prologue.
    float2 a0 = __ldg(&x2[((size_t)b * LL + (TT + 1 + i0)) * E2 + e2]);
    float2 p0 = __ldg(&x2[((size_t)b * LL + (i0 + 1)) * E2 + e2]);
    float2 a1 = __ldg(&x2[((size_t)b * LL + (TT + 1 + i1)) * E2 + e2]);
    float2 p1 = __ldg(&x2[((size_t)b * LL + (i1 + 1)) * E2 + e2]);
    float2 d0 = make_float2(a0.x - p0.x, a0.y - p0.y);
    float2 d1 = make_float2(a1.x - p1.x, a1.y - p1.y);

    const int lbeg = zl * LCH;
    const size_t outrow0 = (size_t)b * LOUT + (TT + 1);

    const float2* __restrict__ sp =
        reinterpret_cast<const float2*>(g_S) +
        ((size_t)b * LL + lbeg + lsub) * E2 + e2;
    float2* __restrict__ q0 = o2 + (outrow0 + (size_t)i0 * LL + lbeg + lsub) * E2 + e2;
    float2* __restrict__ q1 = o2 + (outrow0 + (size_t)i1 * LL + lbeg + lsub) * E2 + e2;

    // --- Wait for producer, then stream ---
    cudaGridDependencySynchronize();

#pragma unroll
    for (int it = 0; it < LCH / 4; it++) {   // 3 iterations
        float2 s = __ldg(sp);
        float2 o0, o1;
        o0.x = fmaf(d0.x, s.x, p0.x);
        o0.y = fmaf(d0.y, s.y, p0.y);
        o1.x = fmaf(d1.x, s.x, p1.x);
        o1.y = fmaf(d1.y, s.y, p1.y);
        __stcs(q0, o0);
        __stcs(q1, o1);
        sp += 4 * E2;
        q0 += 4 * E2;
        q1 += 4 * E2;
    }
}

extern "C" void kernel_launch(void* const* d_in, const int* in_sizes, int n_in,
                              void* d_out, int out_size) {
    const float* x  = (const float*)d_in[0];
    const float* W  = (const float*)d_in[1];
    const float* bv = (const float*)d_in[2];
    float* out = (float*)d_out;

    // Producer: 98304 float4s -> 384 blocks of 256. S-table only.
    prep_kernel<<<(BB * LL * E4 + 255) / 256, 256>>>(x, W, bv);

    // Consumer with programmatic dependent launch.
    cudaLaunchAttribute attr[1];
    attr[0].id = cudaLaunchAttributeProgrammaticStreamSerialization;
    attr[0].val.programmaticStreamSerializationAllowed = 1;

    cudaLaunchConfig_t cfg = {};
    cfg.gridDim  = dim3(NI / G, BB, NZ);   // (83, 16, 16) = 21248 CTAs
    cfg.blockDim = dim3(256, 1, 1);
    cfg.dynamicSmemBytes = 0;
    cfg.stream = 0;
    cfg.attrs = attr;
    cfg.numAttrs = 1;

    cudaLaunchKernelEx(&cfg, blocks_kernel, x, out);
}